// round 13
// baseline (speedup 1.0000x reference)
#include <cuda_runtime.h>

// Heirachical_Loss — closed-form collapse of the hierarchy matmul.
//
// loss = B - sum_i [ 0.5*S_all + 0.25*S100(t) + 0.125*S10(t) + 0.125*outputs[i,t] ]
//
// Single fused kernel: R2 main structure verbatim (best measured 23.6us),
// plus last-block final reduction. The last block reads a FIXED padded
// 4096-float partial range (zero-init device storage; unwritten entries
// stay 0 forever) as 4 front-batched float4s per thread -> one parallel
// memory round-trip, no serialized tail, no second launch (which measured
// ~4.5us of pure fixed overhead). Deterministic: fixed summation order,
// no float atomics; counter auto-wraps so graph replays self-reset.

#define HL_C           1000
#define ROWS_PER_BLOCK 8
#define HL_THREADS     256
#define PAD_PARTIALS   4096                 // fixed padded read range (floats)
#define MAX_BLOCKS     8192

__device__ float        g_hl_partials[MAX_BLOCKS];   // zero-init at module load
__device__ unsigned int g_hl_count = 0;

__global__ void __launch_bounds__(HL_THREADS) hloss_fused(
    const float* __restrict__ outputs,
    const int*   __restrict__ target,
    float*       __restrict__ out,
    int B)
{
    const int warp = threadIdx.x >> 5;
    const int lane = threadIdx.x & 31;
    const int row  = blockIdx.x * ROWS_PER_BLOCK + warp;

    float win = 0.0f;
    if (row < B) {
        const int t = target[row];
        const float4* __restrict__ p =
            (const float4*)(outputs + (size_t)row * HL_C);

        // ---- Phase 1: full-row sum (250 float4 per row, front-batched) ----
        float4 v[7];
#pragma unroll
        for (int it = 0; it < 7; ++it)
            v[it] = p[it * 32 + lane];            // float4 idx 0..223
        float4 vt = make_float4(0.f, 0.f, 0.f, 0.f);
        if (lane < 26)
            vt = p[224 + lane];                   // idx 224..249

        float s = (vt.x + vt.y) + (vt.z + vt.w);
#pragma unroll
        for (int it = 0; it < 7; ++it)
            s += (v[it].x + v[it].y) + (v[it].z + v[it].w);

        // ---- Phase 2: target's 100-block (L1 hit — just loaded) ----
        const int lo100 = (t / 100) * 100;        // 4-aligned
        const int lo10  = (t / 10)  * 10;
        float s100 = 0.f, s10 = 0.f, ot = 0.f;
        if (lane < 25) {
            float4 q = p[(lo100 >> 2) + lane];
            const int e0 = lo100 + lane * 4;
            float vals[4] = { q.x, q.y, q.z, q.w };
#pragma unroll
            for (int m = 0; m < 4; ++m) {
                const int e = e0 + m;
                const float vv = vals[m];
                s100 += vv;
                if ((unsigned)(e - lo10) < 10u) s10 += vv;
                if (e == t)                     ot  = vv;
            }
        }

        float part = 0.5f * s + 0.25f * s100 + 0.125f * s10 + 0.125f * ot;
#pragma unroll
        for (int off = 16; off; off >>= 1)
            part += __shfl_xor_sync(0xffffffffu, part, off);
        win = part;
    }

    // ---- Block reduce: one win per warp -> per-block partial of (1 - win) ----
    __shared__ float ws[ROWS_PER_BLOCK];
    __shared__ bool  s_is_last;
    if (lane == 0)
        ws[warp] = (row < B) ? (1.0f - win) : 0.0f;
    __syncthreads();
    if (threadIdx.x == 0) {
        float acc = 0.f;
#pragma unroll
        for (int w = 0; w < ROWS_PER_BLOCK; ++w) acc += ws[w];
        g_hl_partials[blockIdx.x] = acc;
        __threadfence();
        // atomicInc wraps to 0 when old == gridDim.x-1 -> auto-reset per replay.
        unsigned vcnt = atomicInc(&g_hl_count, gridDim.x - 1u);
        s_is_last = (vcnt == gridDim.x - 1u);
    }
    __syncthreads();
    if (!s_is_last) return;

    // ---- Last block: deterministic final sum over fixed padded range ----
    __threadfence();
    const int tid = threadIdx.x;
    float a = 0.f;
    if (gridDim.x <= PAD_PARTIALS) {
        // 4096 floats = 1024 float4; 4 per thread, front-batched (1 round-trip).
        // Entries >= gridDim.x were never written and are 0 (zero-init .bss).
        const float4* __restrict__ pp = (const float4*)g_hl_partials;
        float4 q[4];
#pragma unroll
        for (int k = 0; k < 4; ++k)
            q[k] = pp[k * HL_THREADS + tid];
#pragma unroll
        for (int k = 0; k < 4; ++k)
            a += (q[k].x + q[k].y) + (q[k].z + q[k].w);
    } else {
        for (int i = tid; i < (int)gridDim.x; i += HL_THREADS)
            a += g_hl_partials[i];
    }
    __shared__ float sm[HL_THREADS];
    sm[tid] = a;
    __syncthreads();
#pragma unroll
    for (int s2 = HL_THREADS / 2; s2; s2 >>= 1) {
        if (tid < s2) sm[tid] += sm[tid + s2];
        __syncthreads();
    }
    if (tid == 0) out[0] = sm[0];
}

extern "C" void kernel_launch(void* const* d_in, const int* in_sizes, int n_in,
                              void* d_out, int out_size)
{
    // metadata order: outputs [B*1000] float32, target [B] int32.
    int i_o = 0, i_t = 1;
    if (n_in >= 2 && in_sizes[1] > in_sizes[0]) { i_o = 1; i_t = 0; }

    const float* outputs = (const float*)d_in[i_o];
    const int*   target  = (const int*)d_in[i_t];
    const int B = in_sizes[i_t];

    int nblocks = (B + ROWS_PER_BLOCK - 1) / ROWS_PER_BLOCK;  // 4096 for B=32768
    if (nblocks > MAX_BLOCKS) nblocks = MAX_BLOCKS;

    hloss_fused<<<nblocks, HL_THREADS>>>(outputs, target, (float*)d_out, B);
}